// round 16
// baseline (speedup 1.0000x reference)
#include <cuda_runtime.h>
#include <cuda_fp16.h>
#include <math.h>
#include <stdint.h>

// ---------------------------------------------------------------------------
// IEBINS — B=2, H=120, W=160, HD=128, CD=192, BN=16, 6 iters
// mma.sync fp16 3-term-split implicit-GEMM convs; cp.async 4-stage pipeline.
// GRU pointwise fused into conv epilogues; softmax/bins fused into ph2 conv.
// ---------------------------------------------------------------------------

#define H_   120
#define W_   160
#define HW   19200
#define NPIX 38400

enum { ACT_NONE = 0, ACT_RELU = 1, ACT_SIG = 2, ACT_TANH = 3 };
enum { EPI_STD = 0, EPI_Z_RH = 1, EPI_GRU = 2 };

// ------------------------- fp32 scratch ------------------------------------
constexpr long OFF_EDGES = 0;          // [2][17][HW]
constexpr long OFF_H     = 652800;     // [NPIX][128] GRU state
constexpr long SCRATCH_TOTAL = OFF_H + (long)NPIX * 128;
__device__ __align__(1024) float g_scratch[SCRATCH_TOTAL];

// ------------------------- fp16 activation arenas (hi / lo planes) ---------
constexpr long A_CD = 0;          // [NPIX][16]
constexpr long A_E1 = 614400;     // [NPIX][128]
constexpr long A_E2 = 5529600;    // [NPIX][128]
constexpr long A_X  = 10444800;   // [NPIX][448]: d(0:256) | ctx(256:448)
constexpr long A_HT = 27648000;   // [NPIX][128] packed h
constexpr long A_RH = 32563200;   // [NPIX][128] packed r*h
constexpr long A_Z  = 37478400;   // [NPIX][128] packed z
constexpr long A_TOT = 42393600;
__device__ __align__(1024) __half g_acthi[A_TOT];
__device__ __align__(1024) __half g_actlo[A_TOT];

// ------------------------- fp16 split-weight arena -------------------------
// layout per conv: [COUT][KH*KW][CIN], hi / lo planes
constexpr long W_E1  = 0;         // 128*784
constexpr long W_E2  = 100352;    // 147456
constexpr long W_E3  = 247808;    // 147456
constexpr long W_E4  = 395264;    // 294912
constexpr long W_ZR1 = 690176;    // 737280 (z | r)
constexpr long W_Q1  = 1427456;   // 368640
constexpr long W_ZR2 = 1796096;   // 737280
constexpr long W_Q2  = 2533376;   // 368640
constexpr long W_P1  = 2902016;   // 147456
constexpr long W_P2  = 3049472;   // 18432 (16 x 1152, unpadded)
constexpr long W_TOT = 3067904;
__device__ __align__(16) __half g_whi[W_TOT];
__device__ __align__(16) __half g_wlo[W_TOT];

// ------------------------- helpers -----------------------------------------
template <int ACT>
__device__ __forceinline__ float epi(float v) {
    if (ACT == ACT_RELU) return fmaxf(v, 0.0f);
    if (ACT == ACT_SIG)  return 1.0f / (1.0f + expf(-v));
    if (ACT == ACT_TANH) return tanhf(v);
    return v;
}
__device__ __forceinline__ void mma16816(float* c, const uint32_t* a, const uint32_t* b) {
    asm volatile(
        "mma.sync.aligned.m16n8k16.row.col.f32.f16.f16.f32 "
        "{%0,%1,%2,%3}, {%4,%5,%6,%7}, {%8,%9}, {%0,%1,%2,%3};\n"
        : "+f"(c[0]), "+f"(c[1]), "+f"(c[2]), "+f"(c[3])
        : "r"(a[0]), "r"(a[1]), "r"(a[2]), "r"(a[3]), "r"(b[0]), "r"(b[1]));
}
__device__ __forceinline__ void ldsm4(uint32_t& r0, uint32_t& r1, uint32_t& r2,
                                      uint32_t& r3, uint32_t a) {
    asm volatile("ldmatrix.sync.aligned.m8n8.x4.shared.b16 {%0,%1,%2,%3}, [%4];"
                 : "=r"(r0), "=r"(r1), "=r"(r2), "=r"(r3) : "r"(a));
}
__device__ __forceinline__ uint32_t smem_u32(const void* p) {
    uint32_t a;
    asm("{ .reg .u64 t; cvta.to.shared.u64 t, %1; cvt.u32.u64 %0, t; }"
        : "=r"(a) : "l"(p));
    return a;
}
__device__ __forceinline__ void cpa16(uint32_t d, const void* s) {
    asm volatile("cp.async.cg.shared.global [%0], [%1], 16;"
                 :: "r"(d), "l"(s) : "memory");
}
__device__ __forceinline__ void cpa16z(uint32_t d, const void* s, int sz) {
    asm volatile("cp.async.cg.shared.global [%0], [%1], 16, %2;"
                 :: "r"(d), "l"(s), "r"(sz) : "memory");
}
#define CP_COMMIT() asm volatile("cp.async.commit_group;" ::: "memory")
#define CP_WAIT1()  asm volatile("cp.async.wait_group 1;" ::: "memory")
#define CP_WAIT2()  asm volatile("cp.async.wait_group 2;" ::: "memory")

__device__ __forceinline__ void split2(float v, __half& h, __half& l) {
    h = __float2half_rn(v);
    l = __float2half_rn(v - __half2float(h));
}
__device__ __forceinline__ uint32_t packhl(float v) {   // hi low16 | lo high16
    __half h, l;
    split2(v, h, l);
    return (uint32_t)(*reinterpret_cast<unsigned short*>(&h))
         | ((uint32_t)(*reinterpret_cast<unsigned short*>(&l)) << 16);
}
__device__ __forceinline__ float join2(__half h, __half l) {
    return __half2float(h) + __half2float(l);
}
__device__ __forceinline__ float joinu(uint32_t u) {
    unsigned short hb = (unsigned short)(u & 0xFFFFu);
    unsigned short lb = (unsigned short)(u >> 16);
    return __half2float(*reinterpret_cast<__half*>(&hb))
         + __half2float(*reinterpret_cast<__half*>(&lb));
}

// ===========================================================================
// fp16 mma implicit-GEMM conv, cp.async 4-stage pipeline, ldmatrix.
// M = COUT(128/blk.y), N = 128 pixels, K in 16-chunks (pos outer, ci inner).
// Dual-source B: channels [0,CSPLIT) from tensor0, rest from tensor1.
// 3-term split: AhBh + AhBl + AlBh (fp32 accum).
// EPI_STD: packed hi/lo store. EPI_Z_RH: y0=z store, y1=r*h fuse.
// EPI_GRU: hn=(1-z)h+zq fuse (writes OFF_H + A_HT).
// ===========================================================================
template <int CSPLIT, int CIN, int COUT, int KH, int KW, int PH, int PW,
          int ACT, int EPI>
__global__ __launch_bounds__(256)
void conv_mma(long in0_off, int in0_cs, long in1_off, int in1_cs,
              long w_off, const float* __restrict__ bias0,
              const float* __restrict__ bias1,
              long out_off, int out_cs, int out_ch0)
{
    constexpr int KTOT  = CIN * KH * KW;
    constexpr int CPC   = CIN / 16;
    constexpr int NITER = KTOT / 16;
    constexpr int STAGE = 24576;
    constexpr int NSTG  = 4;
    static_assert(CIN % 16 == 0 && NITER >= NSTG && CSPLIT % 16 == 0, "bad cfg");

    extern __shared__ __align__(128) char smem[];
    const uint32_t sbase = smem_u32(smem);

    const int tid  = threadIdx.x;
    const int lane = tid & 31;
    const int wid  = tid >> 5;
    const int warp_m = wid >> 2;
    const int warp_n = wid & 3;
    const int g    = lane >> 2;
    const int tg   = lane & 3;
    const int lrow = lane & 15;
    const int lcol = lane >> 4;

    const int n0 = blockIdx.x << 7;
    const int m0 = blockIdx.y << 7;
    const int bb = n0 / HW;
    const int pixbase = bb * HW;

    const int arow = tid & 127;
    const int asel = tid >> 7;
    const __half* wbase =
        (asel ? g_wlo : g_whi) + w_off + (long)(m0 + arow) * KTOT;
    const uint32_t aStsOff = asel * 6144 + arow * 48;

    const int pixl   = tid & 127;
    const int bplane = tid >> 7;
    const int hwp = (n0 - pixbase) + pixl;
    const int py  = hwp / W_;
    const int px  = hwp - py * W_;
    const __half* plane = bplane ? g_actlo : g_acthi;
    const __half* b0 = plane + in0_off;
    const __half* b1 = plane + in1_off;
    const uint32_t bStsOff = 12288 + bplane * 6144 + pixl * 48;

    const uint32_t aLdOff = (warp_m * 64 + lrow) * 48 + lcol * 16;
    const uint32_t bLdOff = 12288 + (warp_n * 32 + lrow) * 48 + lcol * 16;

    float acc[4][4][4];
#pragma unroll
    for (int mt = 0; mt < 4; mt++)
#pragma unroll
        for (int nt = 0; nt < 4; nt++)
#pragma unroll
            for (int e = 0; e < 4; e++) acc[mt][nt][e] = 0.0f;

    auto issue = [&](int it, uint32_t soff) {
        const uint32_t ad = sbase + soff + aStsOff;
        const __half* as = wbase + it * 16;
        cpa16(ad, as);
        cpa16(ad + 16, as + 8);
        const int pos = it / CPC;
        const int cic = it - pos * CPC;
        const int ky  = pos / KW;
        const int kx  = pos - ky * KW;
        const int iy  = py + ky - PH;
        const int ix  = px + kx - PW;
        const bool ok = ((unsigned)iy < (unsigned)H_) && ((unsigned)ix < (unsigned)W_);
        const __half* bs;
        if (ok) {
            const long poff = (long)(pixbase + iy * W_ + ix);
            const int c16 = cic * 16;
            if (CSPLIT > 0 && c16 < CSPLIT)
                bs = b0 + poff * in0_cs + c16;
            else
                bs = b1 + poff * in1_cs + (c16 - CSPLIT);
        } else {
            bs = b1;
        }
        const int sz = ok ? 16 : 0;
        const uint32_t bd = sbase + soff + bStsOff;
        cpa16z(bd, bs, sz);
        cpa16z(bd + 16, bs + 8, sz);
    };

    // prologue: 3 stages in flight
    issue(0, 0);            CP_COMMIT();
    issue(1, STAGE);        CP_COMMIT();
    issue(2, 2 * STAGE);    CP_COMMIT();

    uint32_t cur = 0, nxt = 3 * STAGE;
#pragma unroll 1
    for (int it = 0; it < NITER; ++it) {
        CP_WAIT2();
        __syncthreads();
        if (it + 3 < NITER) issue(it + 3, nxt);
        CP_COMMIT();

        const uint32_t base = sbase + cur;
        uint32_t ah[4][4], al[4][4];
#pragma unroll
        for (int mt = 0; mt < 4; mt++) {
            const uint32_t aa = base + aLdOff + mt * 768;
            ldsm4(ah[mt][0], ah[mt][1], ah[mt][2], ah[mt][3], aa);
            ldsm4(al[mt][0], al[mt][1], al[mt][2], al[mt][3], aa + 6144);
        }
#pragma unroll
        for (int p = 0; p < 2; p++) {
            uint32_t bh[4], bl[4];
            const uint32_t ba = base + bLdOff + p * 768;
            ldsm4(bh[0], bh[1], bh[2], bh[3], ba);
            ldsm4(bl[0], bl[1], bl[2], bl[3], ba + 6144);
#pragma unroll
            for (int f = 0; f < 2; f++) {
                uint32_t bhf[2] = { bh[f], bh[f + 2] };
                uint32_t blf[2] = { bl[f], bl[f + 2] };
                const int nt = p * 2 + f;
#pragma unroll
                for (int mt = 0; mt < 4; mt++) {
                    mma16816(acc[mt][nt], ah[mt], bhf);
                    mma16816(acc[mt][nt], ah[mt], blf);
                    mma16816(acc[mt][nt], al[mt], bhf);
                }
            }
        }
        cur = (cur == 3 * STAGE) ? 0 : cur + STAGE;
        nxt = (nxt == 3 * STAGE) ? 0 : nxt + STAGE;
    }

    // ---- epilogue: bias + act + pack; smem-staged [pixel][ch] ----
    const float* bias = (blockIdx.y == 0) ? bias0 : bias1;
    uint32_t pk[4][4][4];
#pragma unroll
    for (int mt = 0; mt < 4; mt++) {
        const int r0 = warp_m * 64 + mt * 16 + g;
        const float bv0 = __ldg(bias + r0);
        const float bv1 = __ldg(bias + r0 + 8);
#pragma unroll
        for (int nt = 0; nt < 4; nt++) {
            pk[mt][nt][0] = packhl(epi<ACT>(acc[mt][nt][0] + bv0));
            pk[mt][nt][1] = packhl(epi<ACT>(acc[mt][nt][1] + bv0));
            pk[mt][nt][2] = packhl(epi<ACT>(acc[mt][nt][2] + bv1));
            pk[mt][nt][3] = packhl(epi<ACT>(acc[mt][nt][3] + bv1));
        }
    }
    uint32_t* st = reinterpret_cast<uint32_t*>(smem);
    const int pix = tid & 63;
    const int q   = tid >> 6;
#pragma unroll 1
    for (int pass = 0; pass < 2; pass++) {
        __syncthreads();
        if ((warp_n >> 1) == pass) {
#pragma unroll
            for (int mt = 0; mt < 4; mt++) {
                const int r = warp_m * 64 + mt * 16 + g;
#pragma unroll
                for (int nt = 0; nt < 4; nt++) {
                    const int cloc = (warp_n & 1) * 32 + nt * 8 + 2 * tg;
                    st[cloc * 132 + r]           = pk[mt][nt][0];
                    st[(cloc + 1) * 132 + r]     = pk[mt][nt][1];
                    st[cloc * 132 + r + 8]       = pk[mt][nt][2];
                    st[(cloc + 1) * 132 + r + 8] = pk[mt][nt][3];
                }
            }
        }
        __syncthreads();
        const long P = n0 + pass * 64 + pix;
        if (EPI == EPI_STD || (EPI == EPI_Z_RH && blockIdx.y == 0)) {
            const long prow = P * out_cs + out_ch0 + m0 + q * 32;
            __half* oh = g_acthi + out_off + prow;
            __half* ol = g_actlo + out_off + prow;
#pragma unroll
            for (int jp = 0; jp < 4; jp++) {
                uint4 vA = *reinterpret_cast<uint4*>(&st[pix * 132 + q * 32 + jp * 8]);
                uint4 vB = *reinterpret_cast<uint4*>(&st[pix * 132 + q * 32 + jp * 8 + 4]);
                uint4 hv, lv;
                hv.x = __byte_perm(vA.x, vA.y, 0x5410);
                hv.y = __byte_perm(vA.z, vA.w, 0x5410);
                hv.z = __byte_perm(vB.x, vB.y, 0x5410);
                hv.w = __byte_perm(vB.z, vB.w, 0x5410);
                lv.x = __byte_perm(vA.x, vA.y, 0x7632);
                lv.y = __byte_perm(vA.z, vA.w, 0x7632);
                lv.z = __byte_perm(vB.x, vB.y, 0x7632);
                lv.w = __byte_perm(vB.z, vB.w, 0x7632);
                *reinterpret_cast<uint4*>(oh + jp * 8) = hv;
                *reinterpret_cast<uint4*>(ol + jp * 8) = lv;
            }
        } else if (EPI == EPI_Z_RH) {
            // y==1: rh = r * h  -> A_RH (reads h fp32; no race with mainloop)
            const long cbase = P * 128 + q * 32;
#pragma unroll
            for (int jp = 0; jp < 4; jp++) {
                float4 h0 = *reinterpret_cast<float4*>(&g_scratch[OFF_H + cbase + jp * 8]);
                float4 h1 = *reinterpret_cast<float4*>(&g_scratch[OFF_H + cbase + jp * 8 + 4]);
                const float hv[8] = {h0.x, h0.y, h0.z, h0.w, h1.x, h1.y, h1.z, h1.w};
                union { uint4 v; __half h[8]; } oh, ol;
#pragma unroll
                for (int k = 0; k < 8; k++) {
                    const float r = joinu(st[pix * 132 + q * 32 + jp * 8 + k]);
                    split2(r * hv[k], oh.h[k], ol.h[k]);
                }
                *reinterpret_cast<uint4*>(&g_acthi[A_RH + cbase + jp * 8]) = oh.v;
                *reinterpret_cast<uint4*>(&g_actlo[A_RH + cbase + jp * 8]) = ol.v;
            }
        } else if (EPI == EPI_GRU) {
            // hn = (1-z)*h + z*q -> OFF_H (fp32) + A_HT (packed)
            const long cbase = P * 128 + q * 32;
#pragma unroll
            for (int jp = 0; jp < 4; jp++) {
                float4 h0 = *reinterpret_cast<float4*>(&g_scratch[OFF_H + cbase + jp * 8]);
                float4 h1 = *reinterpret_cast<float4*>(&g_scratch[OFF_H + cbase + jp * 8 + 4]);
                const float hv[8] = {h0.x, h0.y, h0.z, h0.w, h1.x, h1.y, h1.z, h1.w};
                union { uint4 v; __half h[8]; } zh, zl, oh, ol;
                zh.v = *reinterpret_cast<const uint4*>(&g_acthi[A_Z + cbase + jp * 8]);
                zl.v = *reinterpret_cast<const uint4*>(&g_actlo[A_Z + cbase + jp * 8]);
                float hn[8];
#pragma unroll
                for (int k = 0; k < 8; k++) {
                    const float qv = joinu(st[pix * 132 + q * 32 + jp * 8 + k]);
                    const float z  = join2(zh.h[k], zl.h[k]);
                    hn[k] = (1.0f - z) * hv[k] + z * qv;
                    split2(hn[k], oh.h[k], ol.h[k]);
                }
                *reinterpret_cast<float4*>(&g_scratch[OFF_H + cbase + jp * 8]) =
                    make_float4(hn[0], hn[1], hn[2], hn[3]);
                *reinterpret_cast<float4*>(&g_scratch[OFF_H + cbase + jp * 8 + 4]) =
                    make_float4(hn[4], hn[5], hn[6], hn[7]);
                *reinterpret_cast<uint4*>(&g_acthi[A_HT + cbase + jp * 8]) = oh.v;
                *reinterpret_cast<uint4*>(&g_actlo[A_HT + cbase + jp * 8]) = ol.v;
            }
        }
    }
}

// ===========================================================================
// Specialized ph2 conv + FUSED softmax/bins: COUT=16, CIN=128, 3x3.
// M=16 x N=128 tile; 3-term. Logits staged fp32 in smem -> per-pixel bins.
// ===========================================================================
__global__ __launch_bounds__(256)
void conv_mma16(long in_off, long w_off, const float* __restrict__ bias,
                float* __restrict__ out, int itr)
{
    constexpr int KTOT = 1152, CPC = 8, NITER = 72;
    constexpr int STAGE = 13824;   // Ahi768 | Alo768 | Bhi6144 | Blo6144
    __shared__ __align__(128) char smem[3 * STAGE];
    const uint32_t sbase = smem_u32(smem);

    const int tid  = threadIdx.x;
    const int lane = tid & 31;
    const int wid  = tid >> 5;
    const int g  = lane >> 2;
    const int tg = lane & 3;

    const int n0 = blockIdx.x << 7;
    const int bb = n0 / HW;
    const int pixbase = bb * HW;

    const int arow  = tid & 15;
    const int ahalf = (tid >> 4) & 1;
    const int asel  = tid >> 5;    // valid when tid<64
    const __half* wb =
        ((asel & 1) ? g_wlo : g_whi) + w_off + (long)arow * KTOT + ahalf * 8;

    const int pixl   = tid & 127;
    const int bplane = tid >> 7;
    const int hwp = (n0 - pixbase) + pixl;
    const int py  = hwp / W_;
    const int px  = hwp - py * W_;
    const __half* bsrc0 = (bplane ? g_actlo : g_acthi) + in_off;
    const uint32_t bStsOff = 1536 + bplane * 6144 + pixl * 48;

    const uint32_t aLdOff = (lane & 15) * 48 + (lane >> 4) * 16;
    const uint32_t bLdOff = 1536 + (wid * 16 + (lane & 15)) * 48 + (lane >> 4) * 16;

    float acc[2][4];
#pragma unroll
    for (int nf = 0; nf < 2; nf++)
#pragma unroll
        for (int e = 0; e < 4; e++) acc[nf][e] = 0.0f;

    auto issue = [&](int it, uint32_t soff) {
        if (tid < 64)
            cpa16(sbase + soff + (asel & 1) * 768 + arow * 48 + ahalf * 16,
                  wb + it * 16);
        const int pos = it / CPC;
        const int cic = it - pos * CPC;
        const int ky  = pos / 3;
        const int kx  = pos - ky * 3;
        const int iy  = py + ky - 1;
        const int ix  = px + kx - 1;
        const bool ok = ((unsigned)iy < (unsigned)H_) && ((unsigned)ix < (unsigned)W_);
        const __half* bs = ok
            ? bsrc0 + (long)(pixbase + iy * W_ + ix) * 128 + cic * 16
            : bsrc0;
        const int sz = ok ? 16 : 0;
        const uint32_t bd = sbase + soff + bStsOff;
        cpa16z(bd, bs, sz);
        cpa16z(bd + 16, bs + 8, sz);
    };

    issue(0, 0);       CP_COMMIT();
    issue(1, STAGE);   CP_COMMIT();

    uint32_t cur = 0, nxt = 2 * STAGE;
#pragma unroll 1
    for (int it = 0; it < NITER; ++it) {
        CP_WAIT1();
        __syncthreads();
        if (it + 2 < NITER) issue(it + 2, nxt);
        CP_COMMIT();

        const uint32_t base = sbase + cur;
        uint32_t ah[4], al[4], bh[4], bl[4];
        ldsm4(ah[0], ah[1], ah[2], ah[3], base + aLdOff);
        ldsm4(al[0], al[1], al[2], al[3], base + aLdOff + 768);
        ldsm4(bh[0], bh[1], bh[2], bh[3], base + bLdOff);
        ldsm4(bl[0], bl[1], bl[2], bl[3], base + bLdOff + 6144);
#pragma unroll
        for (int nf = 0; nf < 2; nf++) {
            uint32_t bhf[2] = { bh[nf], bh[nf + 2] };
            uint32_t blf[2] = { bl[nf], bl[nf + 2] };
            mma16816(acc[nf], ah, bhf);
            mma16816(acc[nf], ah, blf);
            mma16816(acc[nf], al, bhf);
        }
        cur = (cur == 2 * STAGE) ? 0 : cur + STAGE;
        nxt = (nxt == 2 * STAGE) ? 0 : nxt + STAGE;
    }

    // ---- stage logits fp32 in smem [128 pixels][17 stride] ----
    float* st = reinterpret_cast<float*>(smem);
    const float bv0 = __ldg(bias + g);
    const float bv1 = __ldg(bias + g + 8);
    __syncthreads();   // mainloop smem fully consumed
#pragma unroll
    for (int nf = 0; nf < 2; nf++) {
        const int pl = wid * 16 + nf * 8 + 2 * tg;
        st[pl * 17 + g]           = acc[nf][0] + bv0;
        st[(pl + 1) * 17 + g]     = acc[nf][1] + bv0;
        st[pl * 17 + g + 8]       = acc[nf][2] + bv1;
        st[(pl + 1) * 17 + g + 8] = acc[nf][3] + bv1;
    }
    __syncthreads();

    // ---- fused softmax / depth_r / uncertainty / label / bin update ----
    if (tid < 128) {
        const int p = n0 + tid;
        const int b = p / HW, hw = p - b * HW;
        const long cdo = A_CD + (long)p * 16;
        float* edp = g_scratch + OFF_EDGES + (long)b * 17 * HW + hw;

        float l[16], cd[16];
        float m = -1e30f;
#pragma unroll
        for (int i = 0; i < 16; i++) { l[i] = st[tid * 17 + i]; m = fmaxf(m, l[i]); }
        float s = 0.0f;
#pragma unroll
        for (int i = 0; i < 16; i++) { l[i] = expf(l[i] - m); s += l[i]; }
        const float inv = 1.0f / s;
        float dr = 0.0f;
#pragma unroll
        for (int i = 0; i < 16; i++) {
            cd[i] = join2(g_acthi[cdo + i], g_actlo[cdo + i]);
            dr += l[i] * cd[i];
        }
        dr *= inv;
        float var = 0.0f;
#pragma unroll
        for (int i = 0; i < 16; i++) { const float d = cd[i] - dr; var += l[i] * d * d; }
        var *= inv;
        const float unc = sqrtf(var);

        out[(0 * 6 + itr) * NPIX + p] = dr;
        out[(2 * 6 + itr) * NPIX + p] = unc;

        int cnt = 0;
#pragma unroll
        for (int j = 1; j <= 15; j++) cnt += (dr >= edp[j * HW]) ? 1 : 0;
        const int label = (dr >= edp[16 * HW]) ? 0 : cnt;
        out[(1 * 6 + itr) * NPIX + p] = cd[label];

        const float start = fmaxf(dr - 0.5f * unc, 0.0f);
        const float delta = unc * (1.0f / 16.0f);
        float cum = start;
        float eprev = fminf(fmaxf(cum, 0.0f), 80.0f);
        edp[0] = eprev;
#pragma unroll
        for (int i = 1; i <= 16; i++) {
            cum += delta;
            const float e = fminf(fmaxf(cum, 0.0f), 80.0f);
            edp[i * HW] = e;
            split2(0.5f * (eprev + e), g_acthi[cdo + i - 1], g_actlo[cdo + i - 1]);
            eprev = e;
        }
    }
}

// ------------------------- setup kernels -----------------------------------
__global__ void split_w_kernel(const float* __restrict__ w, long off,
                               int rows, int cin, int khw) {
    const int ktot = cin * khw;
    const long n = (long)rows * ktot;
    const long i = (long)blockIdx.x * blockDim.x + threadIdx.x;
    if (i >= n) return;
    const int co  = (int)(i / ktot);
    const int rem = (int)(i - (long)co * ktot);
    const int pos = rem / cin;
    const int ci  = rem - pos * cin;
    const float x = w[(long)co * ktot + (long)ci * khw + pos];
    split2(x, g_whi[off + i], g_wlo[off + i]);
}
__global__ void setup_bins_kernel() {
    const int p = blockIdx.x * blockDim.x + threadIdx.x;
    if (p >= NPIX) return;
    const int b = p / HW, hw = p - b * HW;
    float* ed = g_scratch + OFF_EDGES + (long)b * 17 * HW + hw;
#pragma unroll
    for (int j = 0; j < 17; j++) ed[j * HW] = 5.0f * j;
#pragma unroll
    for (int i = 0; i < 16; i++)
        split2(2.5f + 5.0f * i, g_acthi[A_CD + (long)p * 16 + i],
               g_actlo[A_CD + (long)p * 16 + i]);
}
__global__ void copy_ctx_kernel(const float* __restrict__ ctx) {
    __shared__ float t[192 * 33];
    const int p0 = blockIdx.x * 32;
    const int b = p0 / HW;
    const int hw = p0 - b * HW;
    const float* src = ctx + (long)b * 192 * HW + hw;
    for (int k = threadIdx.x; k < 192 * 32; k += 256) {
        const int c = k >> 5, w = k & 31;
        t[c * 33 + w] = src[(long)c * HW + w];
    }
    __syncthreads();
    for (int k = threadIdx.x; k < 32 * 192; k += 256) {
        const int w = k / 192, c = k - w * 192;
        const long o = A_X + (long)(p0 + w) * 448 + 256 + c;
        split2(t[c * 33 + w], g_acthi[o], g_actlo[o]);
    }
}
__global__ void copy_h_kernel(const float* __restrict__ h0) {
    __shared__ float t[128 * 33];
    const int p0 = blockIdx.x * 32;
    const int b = p0 / HW;
    const int hw = p0 - b * HW;
    const float* src = h0 + (long)b * 128 * HW + hw;
    for (int k = threadIdx.x; k < 128 * 32; k += 256) {
        const int c = k >> 5, w = k & 31;
        t[c * 33 + w] = src[(long)c * HW + w];
    }
    __syncthreads();
    for (int k = threadIdx.x; k < 32 * 128; k += 256) {
        const int w = k >> 7, c = k & 127;
        const float v = t[c * 33 + w];
        g_scratch[OFF_H + (long)(p0 + w) * 128 + c] = v;
        const long o = A_HT + (long)(p0 + w) * 128 + c;
        split2(v, g_acthi[o], g_actlo[o]);
    }
}

// ------------------------- launch ------------------------------------------
extern "C" void kernel_launch(void* const* d_in, const int* in_sizes, int n_in,
                              void* d_out, int out_size)
{
    (void)in_sizes; (void)n_in; (void)out_size;
    const float* context = (const float*)d_in[1];
    const float* gruh    = (const float*)d_in[2];
    const float* e1w = (const float*)d_in[3];  const float* e1b = (const float*)d_in[4];
    const float* e2w = (const float*)d_in[5];  const float* e2b = (const float*)d_in[6];
    const float* e3w = (const float*)d_in[7];  const float* e3b = (const float*)d_in[8];
    const float* e4w = (const float*)d_in[9];  const float* e4b = (const float*)d_in[10];
    const float* z1w = (const float*)d_in[11]; const float* z1b = (const float*)d_in[12];
    const float* r1w = (const float*)d_in[13]; const float* r1b = (const float*)d_in[14];
    const float* q1w = (const float*)d_in[15]; const float* q1b = (const float*)d_in[16];
    const float* z2w = (const float*)d_in[17]; const float* z2b = (const float*)d_in[18];
    const float* r2w = (const float*)d_in[19]; const float* r2b = (const float*)d_in[20];
    const float* q2w = (const float*)d_in[21]; const float* q2b = (const float*)d_in[22];
    const float* p1w = (const float*)d_in[23]; const float* p1b = (const float*)d_in[24];
    const float* p2w = (const float*)d_in[25]; const float* p2b = (const float*)d_in[26];
    float* out = (float*)d_out;

    constexpr int SMEM_DYN = 98304;   // 4 x 24576B stages
    auto fe1  = conv_mma<0, 16, 128, 7, 7, 3, 3, ACT_RELU, EPI_STD>;
    auto fc33 = conv_mma<0, 128, 128, 3, 3, 1, 1, ACT_RELU, EPI_STD>;
    auto fe4  = conv_mma<0, 128, 256, 3, 3, 1, 1, ACT_RELU, EPI_STD>;
    auto fzr1 = conv_mma<128, 576, 256, 1, 5, 0, 2, ACT_SIG, EPI_Z_RH>;
    auto fq1  = conv_mma<128, 576, 128, 1, 5, 0, 2, ACT_TANH, EPI_GRU>;
    auto fzr2 = conv_mma<128, 576, 256, 5, 1, 2, 0, ACT_SIG, EPI_Z_RH>;
    auto fq2  = conv_mma<128, 576, 128, 5, 1, 2, 0, ACT_TANH, EPI_GRU>;
    cudaFuncSetAttribute(fe1,  cudaFuncAttributeMaxDynamicSharedMemorySize, SMEM_DYN);
    cudaFuncSetAttribute(fc33, cudaFuncAttributeMaxDynamicSharedMemorySize, SMEM_DYN);
    cudaFuncSetAttribute(fe4,  cudaFuncAttributeMaxDynamicSharedMemorySize, SMEM_DYN);
    cudaFuncSetAttribute(fzr1, cudaFuncAttributeMaxDynamicSharedMemorySize, SMEM_DYN);
    cudaFuncSetAttribute(fq1,  cudaFuncAttributeMaxDynamicSharedMemorySize, SMEM_DYN);
    cudaFuncSetAttribute(fzr2, cudaFuncAttributeMaxDynamicSharedMemorySize, SMEM_DYN);
    cudaFuncSetAttribute(fq2,  cudaFuncAttributeMaxDynamicSharedMemorySize, SMEM_DYN);

    const dim3 blk(256);
    const int NT = NPIX / 128;
    const int TB = NPIX / 32;

    setup_bins_kernel<<<(NPIX + 255) / 256, 256>>>();
    copy_ctx_kernel<<<TB, 256>>>(context);
    copy_h_kernel<<<TB, 256>>>(gruh);

    auto SW = [&](const float* w, long off, int rows, int cin, int khw) {
        const long n = (long)rows * cin * khw;
        split_w_kernel<<<(int)((n + 255) / 256), 256>>>(w, off, rows, cin, khw);
    };
    SW(e1w, W_E1, 128, 16, 49);
    SW(e2w, W_E2, 128, 128, 9);
    SW(e3w, W_E3, 128, 128, 9);
    SW(e4w, W_E4, 256, 128, 9);
    SW(z1w, W_ZR1,           128, 576, 5);
    SW(r1w, W_ZR1 + 368640,  128, 576, 5);
    SW(q1w, W_Q1, 128, 576, 5);
    SW(z2w, W_ZR2,           128, 576, 5);
    SW(r2w, W_ZR2 + 368640,  128, 576, 5);
    SW(q2w, W_Q2, 128, 576, 5);
    SW(p1w, W_P1, 128, 128, 9);
    SW(p2w, W_P2, 16, 128, 9);          // unpadded 16 rows

    for (int it = 0; it < 6; ++it) {
        // encoder (encd4 writes d into A_X channels 0..255)
        fe1 <<<dim3(NT, 1), blk, SMEM_DYN>>>(A_CD, 16, A_CD, 16, W_E1, e1b, e1b, A_E1, 128, 0);
        fc33<<<dim3(NT, 1), blk, SMEM_DYN>>>(A_E1, 128, A_E1, 128, W_E2, e2b, e2b, A_E2, 128, 0);
        fc33<<<dim3(NT, 1), blk, SMEM_DYN>>>(A_E2, 128, A_E2, 128, W_E3, e3b, e3b, A_E1, 128, 0);
        fe4 <<<dim3(NT, 2), blk, SMEM_DYN>>>(A_E1, 128, A_E1, 128, W_E4, e4b, e4b + 128, A_X, 448, 0);

        // GRU horizontal: z|r conv (y1 fuses rh), then q conv (fuses update)
        fzr1<<<dim3(NT, 2), blk, SMEM_DYN>>>(A_HT, 128, A_X, 448, W_ZR1, z1b, r1b, A_Z, 128, 0);
        fq1 <<<dim3(NT, 1), blk, SMEM_DYN>>>(A_RH, 128, A_X, 448, W_Q1, q1b, q1b, A_HT, 128, 0);

        // GRU vertical
        fzr2<<<dim3(NT, 2), blk, SMEM_DYN>>>(A_HT, 128, A_X, 448, W_ZR2, z2b, r2b, A_Z, 128, 0);
        fq2 <<<dim3(NT, 1), blk, SMEM_DYN>>>(A_RH, 128, A_X, 448, W_Q2, q2b, q2b, A_HT, 128, 0);

        // PHead: p1 conv then fused ph2 + softmax/bins
        fc33<<<dim3(NT, 1), blk, SMEM_DYN>>>(A_HT, 128, A_HT, 128, W_P1, p1b, p1b, A_E1, 128, 0);
        conv_mma16<<<NT, blk>>>(A_E1, W_P2, p2b, out, it);
    }
}